// round 11
// baseline (speedup 1.0000x reference)
#include <cuda_runtime.h>
#include <cuda_bf16.h>
#include <math.h>
#include <stdint.h>

// ---------------- problem constants ----------------
#define N_PATCH 676          // 26*26
#define DIMV    384
#define M_LIB   100000
#define FMAP    26
#define IMG     224
#define KSIZE   33
#define KHALF   16
#define NCAND   8

#define TILE_M  128          // lib rows per CTA
#define TILE_N  128          // patch cols per CTA
#define BK      64           // K slice per cp.async stage
#define NKK     (DIMV / BK)  // 6
#define NBLK_M  ((M_LIB + TILE_M - 1) / TILE_M)   // 782
#define NBLK_N  ((N_PATCH + TILE_N - 1) / TILE_N) // 6
#define NTHREADS 256

// smem row pitch for BK=64 bf16: 128B data + 16B pad = 144B
#define PITCH   144

#define OFF_Y2     0                          // 128 floats = 512
#define OFF_MINCOL 512                        // 128 u64 = 1024
#define OFF_A0     2048
#define OFF_A1     (OFF_A0 + TILE_M * PITCH)  // +18432
#define OFF_B0     (OFF_A1 + TILE_M * PITCH)
#define OFF_B1     (OFF_B0 + TILE_N * PITCH)
#define SMEM_GEMM  (OFF_B1 + TILE_N * PITCH)  // 75776 (~74KB) -> 2 CTAs/SM

// ---------------- device scratch ----------------
__device__ __align__(16) __nv_bfloat16 g_libbf[(size_t)M_LIB * DIMV];
__device__ __align__(16) __nv_bfloat16 g_patchbf[N_PATCH * DIMV];
__device__ unsigned long long g_min[N_PATCH];
__device__ float              g_x2[N_PATCH];
__device__ float              g_y2[M_LIB];
__device__ float              g_minval[N_PATCH];
__device__ float              g_s_star;
__device__ int                g_sidx;
__device__ int                g_mstar;
__device__ unsigned long long g_wpack[M_LIB];

// ---------------- helpers ----------------
__device__ __forceinline__ unsigned int fenc(float f) {
    unsigned int u = __float_as_uint(f);
    return (u & 0x80000000u) ? ~u : (u | 0x80000000u);
}
__device__ __forceinline__ float fdec(unsigned int k) {
    unsigned int u = (k & 0x80000000u) ? (k ^ 0x80000000u) : ~k;
    return __uint_as_float(u);
}
__device__ __forceinline__ uint32_t smem_u32(const void* p) {
    uint32_t a;
    asm("{ .reg .u64 t; cvta.to.shared.u64 t, %1; cvt.u32.u64 %0, t; }" : "=r"(a) : "l"(p));
    return a;
}
__device__ __forceinline__ void ldsm4(uint32_t a, uint32_t& r0, uint32_t& r1, uint32_t& r2, uint32_t& r3) {
    asm volatile("ldmatrix.sync.aligned.m8n8.x4.shared.b16 {%0,%1,%2,%3}, [%4];"
                 : "=r"(r0), "=r"(r1), "=r"(r2), "=r"(r3) : "r"(a));
}
__device__ __forceinline__ void mma16816(float* c, uint32_t a0, uint32_t a1, uint32_t a2, uint32_t a3,
                                         uint32_t b0, uint32_t b1) {
    asm volatile("mma.sync.aligned.m16n8k16.row.col.f32.bf16.bf16.f32 "
                 "{%0,%1,%2,%3}, {%4,%5,%6,%7}, {%8,%9}, {%0,%1,%2,%3};"
                 : "+f"(c[0]), "+f"(c[1]), "+f"(c[2]), "+f"(c[3])
                 : "r"(a0), "r"(a1), "r"(a2), "r"(a3), "r"(b0), "r"(b1));
}
__device__ __forceinline__ void cpa16(uint32_t dst, const void* src, int ok) {
    asm volatile("cp.async.cg.shared.global [%0], [%1], 16, %2;"
                 :: "r"(dst), "l"(src), "r"(ok ? 16 : 0) : "memory");
}
#define CP_COMMIT() asm volatile("cp.async.commit_group;" ::: "memory")
#define CP_WAIT1()  asm volatile("cp.async.wait_group 1;" ::: "memory")
#define CP_WAIT0()  asm volatile("cp.async.wait_group 0;" ::: "memory")

// ---------------- fp32 -> bf16 + squared norms (warp per row); optional g_min init ----------------
__global__ void k_convert(const float* __restrict__ src, __nv_bfloat16* __restrict__ dst,
                          float* __restrict__ norms, int rows, int init_min) {
    int warp = (blockIdx.x * blockDim.x + threadIdx.x) >> 5;
    int lane = threadIdx.x & 31;
    if (warp >= rows) return;
    if (init_min && lane == 1 && warp < N_PATCH) g_min[warp] = 0xFFFFFFFFFFFFFFFFull;
    const float4* p = (const float4*)(src + (size_t)warp * DIMV);
    __nv_bfloat162* q = (__nv_bfloat162*)(dst + (size_t)warp * DIMV);
    float s = 0.f;
    #pragma unroll 3
    for (int i = lane; i < DIMV / 4; i += 32) {
        float4 v = p[i];
        s += v.x * v.x + v.y * v.y + v.z * v.z + v.w * v.w;
        q[i * 2]     = __floats2bfloat162_rn(v.x, v.y);
        q[i * 2 + 1] = __floats2bfloat162_rn(v.z, v.w);
    }
    #pragma unroll
    for (int o = 16; o; o >>= 1) s += __shfl_xor_sync(0xFFFFFFFFu, s, o);
    if (lane == 0) norms[warp] = s;
}

// ---------------- streaming bf16 HMMA GEMM + per-patch min ----------------
// 256 threads, 8 warps (2M x 4N), warp tile 64(M) x 32(N), CTA 128M x 128N.
// K streamed in 6 BK=64 slices, cp.async double-buffered. 2 CTAs/SM for pipe overlap.
__global__ __launch_bounds__(NTHREADS, 2) void k_gemm_bf16() {
    extern __shared__ char smem[];
    const uint32_t sb = smem_u32(smem);
    const int tid  = threadIdx.x;
    const int wid  = tid >> 5;
    const int lane = tid & 31;
    const int m0   = blockIdx.y * TILE_M;
    const int n0   = blockIdx.x * TILE_N;
    const int wm   = wid & 1;        // 2 warps in M (64 rows each)
    const int wn   = wid >> 1;       // 4 warps in N (32 cols each)

    if (tid < TILE_M) {
        int m = m0 + tid;
        *(float*)(smem + OFF_Y2 + tid * 4) = (m < M_LIB) ? g_y2[m] : __int_as_float(0x7F800000);
    }
    if (tid < TILE_N) *(unsigned long long*)(smem + OFF_MINCOL + tid * 8) = 0xFFFFFFFFFFFFFFFFull;

    const int r0 = tid >> 3;         // 0..31
    const int cu = tid & 7;          // 16B unit within row

    auto load_stage = [&](int kk, uint32_t aOff, uint32_t bOff) {
        const int kcol = kk * BK + cu * 8;
        #pragma unroll
        for (int i = 0; i < 4; i++) {
            int r = r0 + i * 32;
            int m = m0 + r;
            const void* s = g_libbf + (size_t)(m < M_LIB ? m : 0) * DIMV + kcol;
            cpa16(sb + aOff + r * PITCH + cu * 16, s, m < M_LIB);
        }
        #pragma unroll
        for (int i = 0; i < 4; i++) {
            int r = r0 + i * 32;
            int n = n0 + r;
            const void* s = g_patchbf + (size_t)(n < N_PATCH ? n : 0) * DIMV + kcol;
            cpa16(sb + bOff + r * PITCH + cu * 16, s, n < N_PATCH);
        }
        CP_COMMIT();
    };

    const uint32_t aRow = lane & 15, aSel = lane >> 4;
    uint32_t aRel[4];
    #pragma unroll
    for (int mt = 0; mt < 4; mt++)
        aRel[mt] = (wm * 64 + mt * 16 + aRow) * PITCH + aSel * 16;
    const uint32_t bRow = (lane & 7) + ((lane >> 4) << 3);
    const uint32_t bSel = (lane >> 3) & 1;
    uint32_t bRel[2];
    #pragma unroll
    for (int nt = 0; nt < 2; nt++)
        bRel[nt] = (wn * 32 + nt * 16 + bRow) * PITCH + bSel * 16;

    float acc[4][4][4];
    #pragma unroll
    for (int mt = 0; mt < 4; mt++)
        #pragma unroll
        for (int t = 0; t < 4; t++)
            #pragma unroll
            for (int e = 0; e < 4; e++) acc[mt][t][e] = 0.f;

    load_stage(0, OFF_A0, OFF_B0);

    int cur = 0;
    #pragma unroll 1
    for (int kk = 0; kk < NKK; kk++) {
        if (kk + 1 < NKK)
            load_stage(kk + 1, cur ? OFF_A0 : OFF_A1, cur ? OFF_B0 : OFF_B1);
        if (kk + 1 < NKK) CP_WAIT1(); else CP_WAIT0();
        __syncthreads();

        const uint32_t aBuf = sb + (cur ? OFF_A1 : OFF_A0);
        const uint32_t bBuf = sb + (cur ? OFF_B1 : OFF_B0);
        #pragma unroll
        for (int ks = 0; ks < BK / 16; ks++) {
            const uint32_t koff = ks * 32;
            uint32_t a[4][4];
            #pragma unroll
            for (int mt = 0; mt < 4; mt++)
                ldsm4(aBuf + aRel[mt] + koff, a[mt][0], a[mt][1], a[mt][2], a[mt][3]);
            uint32_t b[2][4];
            #pragma unroll
            for (int nt = 0; nt < 2; nt++)
                ldsm4(bBuf + bRel[nt] + koff, b[nt][0], b[nt][1], b[nt][2], b[nt][3]);
            #pragma unroll
            for (int mt = 0; mt < 4; mt++)
                #pragma unroll
                for (int nt = 0; nt < 2; nt++) {
                    mma16816(acc[mt][nt * 2],     a[mt][0], a[mt][1], a[mt][2], a[mt][3], b[nt][0], b[nt][1]);
                    mma16816(acc[mt][nt * 2 + 1], a[mt][0], a[mt][1], a[mt][2], a[mt][3], b[nt][2], b[nt][3]);
                }
        }
        __syncthreads();
        cur ^= 1;
    }

    // epilogue
    const int g  = lane >> 2;
    const int c2 = (lane & 3) * 2;
    float y2r[4][2];
    unsigned int mrow[4][2];
    #pragma unroll
    for (int mt = 0; mt < 4; mt++) {
        int ml = wm * 64 + mt * 16 + g;
        y2r[mt][0] = *(const float*)(smem + OFF_Y2 + ml * 4);
        y2r[mt][1] = *(const float*)(smem + OFF_Y2 + (ml + 8) * 4);
        mrow[mt][0] = (unsigned int)(m0 + ml);
        mrow[mt][1] = (unsigned int)(m0 + ml + 8);
    }
    #pragma unroll
    for (int t = 0; t < 4; t++) {
        #pragma unroll
        for (int j = 0; j < 2; j++) {
            unsigned long long p = 0xFFFFFFFFFFFFFFFFull;
            #pragma unroll
            for (int mt = 0; mt < 4; mt++) {
                float v0 = fmaf(-2.f, acc[mt][t][j],     y2r[mt][0]);
                float v1 = fmaf(-2.f, acc[mt][t][j + 2], y2r[mt][1]);
                unsigned long long p0 = ((unsigned long long)fenc(v0) << 32) | mrow[mt][0];
                unsigned long long p1 = ((unsigned long long)fenc(v1) << 32) | mrow[mt][1];
                p = min(p, min(p0, p1));
            }
            #pragma unroll
            for (int o = 4; o <= 16; o <<= 1)
                p = min(p, __shfl_xor_sync(0xFFFFFFFFu, p, o));
            if (lane < 4) {
                int nb = wn * 32 + t * 8 + c2 + j;
                atomicMin((unsigned long long*)(smem + OFF_MINCOL + nb * 8), p);
            }
        }
    }
    __syncthreads();
    if (tid < TILE_N) {
        int n = n0 + tid;
        if (n < N_PATCH)
            atomicMin(&g_min[n], *(unsigned long long*)(smem + OFF_MINCOL + tid * 8));
    }
}

// ---------------- reduce: min_val, argmax -> s_idx, s_star, m_star ----------------
__global__ __launch_bounds__(1024) void k_reduce() {
    __shared__ unsigned long long sh[1024];
    int t = threadIdx.x;
    unsigned long long pk = 0ull;
    if (t < N_PATCH) {
        unsigned long long p = g_min[t];
        float score = fdec((unsigned int)(p >> 32));
        float d = sqrtf(fmaxf(g_x2[t] + score, 0.f));
        g_minval[t] = d;
        pk = ((unsigned long long)fenc(d) << 32) | (unsigned int)(0xFFFFFFFFu - t);
    }
    sh[t] = pk;
    __syncthreads();
    for (int o = 512; o; o >>= 1) {
        if (t < o) sh[t] = max(sh[t], sh[t + o]);
        __syncthreads();
    }
    if (t == 0) {
        unsigned long long w = sh[0];
        int sidx = (int)(0xFFFFFFFFu - (unsigned int)(w & 0xFFFFFFFFu));
        g_sidx = sidx;
        g_s_star = fdec((unsigned int)(w >> 32));
        g_mstar = (int)(unsigned int)(g_min[sidx] & 0xFFFFFFFFu);
    }
}

// ---------------- w_dist on bf16 lib (warp per row) — nominates candidates only ----------------
__global__ void k_wdist_bf16() {
    int warp = (blockIdx.x * blockDim.x + threadIdx.x) >> 5;
    int lane = threadIdx.x & 31;
    if (warp >= M_LIB) return;
    const uint2* pm = (const uint2*)(g_libbf + (size_t)g_mstar * DIMV);   // 4 bf16 per uint2
    const uint2* pb = (const uint2*)(g_libbf + (size_t)warp * DIMV);
    float s = 0.f;
    #pragma unroll 3
    for (int i = lane; i < DIMV / 4; i += 32) {
        uint2 am = pm[i], ab = pb[i];
        float2 m0 = __bfloat1622float2(*(__nv_bfloat162*)&am.x);
        float2 m1 = __bfloat1622float2(*(__nv_bfloat162*)&am.y);
        float2 b0 = __bfloat1622float2(*(__nv_bfloat162*)&ab.x);
        float2 b1 = __bfloat1622float2(*(__nv_bfloat162*)&ab.y);
        float d0 = m0.x - b0.x, d1 = m0.y - b0.y, d2 = m1.x - b1.x, d3 = m1.y - b1.y;
        s += d0 * d0 + d1 * d1 + d2 * d2 + d3 * d3;
    }
    #pragma unroll
    for (int o = 16; o; o >>= 1) s += __shfl_xor_sync(0xFFFFFFFFu, s, o);
    if (lane == 0)
        g_wpack[warp] = ((unsigned long long)fenc(sqrtf(s)) << 32) | (unsigned int)warp;
}

// ---------------- top-8 candidates (bf16 keys) -> exact fp32 re-rank -> scalar s ----------------
__global__ __launch_bounds__(1024) void k_top8_scalar(const float* __restrict__ A,
                                                      const float* __restrict__ B,
                                                      float* __restrict__ out) {
    __shared__ unsigned long long sh[1024];
    __shared__ int cand[NCAND];
    __shared__ float cd[NCAND];      // exact ||lib[mstar]-lib[cand]||
    __shared__ float td[NCAND];      // exact ||patch[sidx]-lib[cand]||
    int t = threadIdx.x;

    int ex[NCAND];
    #pragma unroll
    for (int i = 0; i < NCAND; i++) ex[i] = -1;

    for (int pass = 0; pass < NCAND; pass++) {
        unsigned long long local = 0xFFFFFFFFFFFFFFFFull;
        for (int m = t; m < M_LIB; m += 1024) {
            unsigned long long p = g_wpack[m];
            int idx = (int)(unsigned int)(p & 0xFFFFFFFFu);
            bool skip = false;
            #pragma unroll
            for (int i = 0; i < NCAND; i++) skip |= (idx == ex[i]);
            if (!skip) local = min(local, p);
        }
        sh[t] = local;
        __syncthreads();
        for (int o = 512; o; o >>= 1) {
            if (t < o) sh[t] = min(sh[t], sh[t + o]);
            __syncthreads();
        }
        int widx = (int)(unsigned int)(sh[0] & 0xFFFFFFFFu);
        if (t == 0) cand[pass] = widx;
        ex[pass] = widx;
        __syncthreads();
    }

    // exact fp32 distances for the 8 candidates (warp w -> candidate w)
    int warp = t >> 5, lane = t & 31;
    if (warp < NCAND) {
        int nn = cand[warp];
        const float* pm = B + (size_t)g_mstar * DIMV;
        const float* pa = A + (size_t)g_sidx * DIMV;
        const float* pb = B + (size_t)nn * DIMV;
        float sw = 0.f, st = 0.f;
        for (int i = lane; i < DIMV; i += 32) {
            float b = pb[i];
            float dw = pm[i] - b;
            float dt = pa[i] - b;
            sw += dw * dw;
            st += dt * dt;
        }
        #pragma unroll
        for (int o = 16; o; o >>= 1) {
            sw += __shfl_xor_sync(0xFFFFFFFFu, sw, o);
            st += __shfl_xor_sync(0xFFFFFFFFu, st, o);
        }
        if (lane == 0) { cd[warp] = sqrtf(sw); td[warp] = sqrtf(st); }
    }
    __syncthreads();
    if (t == 0) {
        // selection-sort 8 by (cd asc, idx asc); take ranks 1 and 2
        int order[NCAND];
        #pragma unroll
        for (int i = 0; i < NCAND; i++) order[i] = i;
        for (int i = 0; i < 3; i++) {
            int best = i;
            for (int j = i + 1; j < NCAND; j++) {
                int a = order[j], b = order[best];
                if (cd[a] < cd[b] || (cd[a] == cd[b] && cand[a] < cand[b])) best = j;
            }
            int tmp = order[i]; order[i] = order[best]; order[best] = tmp;
        }
        float sd1 = td[order[1]], sd2 = td[order[2]];
        float Ds = sqrtf((float)DIMV);
        float sstar = g_s_star;
        float w = 1.f - expf(sstar / Ds) / (expf(sd1 / Ds) + expf(sd2 / Ds));
        out[0] = w * sstar;
    }
}

// ---------------- fused seg-map: out = W * M * W^T  (W = gauss(reflect) o bilinear) ----------------
__device__ __forceinline__ int reflect_idx(int i) {
    if (i < 0) i = -i;
    if (i > IMG - 1) i = 2 * (IMG - 1) - i;
    return i;
}

__global__ __launch_bounds__(256) void k_smap(float* __restrict__ out) {
    __shared__ float sK[KSIZE];
    __shared__ float sW[IMG * FMAP];     // 23296 B
    __shared__ float sT[FMAP * IMG];     // 23296 B
    int t = threadIdx.x;

    if (t == 0) {
        double k[KSIZE]; double s = 0.0;
        for (int i = 0; i < KSIZE; i++) {
            double x = (double)i - (KSIZE - 1) / 2.0;
            k[i] = exp(-0.5 * (x / 4.0) * (x / 4.0));
            s += k[i];
        }
        for (int i = 0; i < KSIZE; i++) sK[i] = (float)(k[i] / s);
    }
    __syncthreads();

    // W[o][f] = sum_k k1d[k] * bilinear_weight(row reflect(o+k-16), fmap index f)
    const float scale = (float)FMAP / (float)IMG;
    for (int idx = t; idx < IMG * FMAP; idx += 256) {
        int o = idx / FMAP, f = idx % FMAP;
        float w = 0.f;
        #pragma unroll 1
        for (int k = 0; k < KSIZE; k++) {
            int i = reflect_idx(o + k - KHALF);
            float sy = (i + 0.5f) * scale - 0.5f;
            int y0 = (int)floorf(sy);
            float wy = sy - (float)y0;
            int y0c = min(max(y0, 0), FMAP - 1);
            int y1c = min(max(y0 + 1, 0), FMAP - 1);
            float contrib = ((y0c == f) ? (1.f - wy) : 0.f) + ((y1c == f) ? wy : 0.f);
            w += sK[k] * contrib;
        }
        sW[idx] = w;
    }
    __syncthreads();

    // T[f][o] = sum_g M[f][g] * W[o][g]
    for (int idx = t; idx < FMAP * IMG; idx += 256) {
        int f = idx / IMG, o = idx % IMG;
        float s = 0.f;
        #pragma unroll
        for (int g = 0; g < FMAP; g++)
            s += g_minval[f * FMAP + g] * sW[o * FMAP + g];
        sT[f * IMG + o] = s;
    }
    __syncthreads();

    // out[y][x] = sum_f W[y][f] * T[f][x]
    for (int idx = t; idx < IMG * IMG; idx += 256) {
        int y = idx / IMG, x = idx % IMG;
        float s = 0.f;
        #pragma unroll
        for (int f = 0; f < FMAP; f++)
            s += sW[y * FMAP + f] * sT[f * IMG + x];
        out[idx] = s;
    }
}

// ---------------- launch ----------------
extern "C" void kernel_launch(void* const* d_in, const int* in_sizes, int n_in,
                              void* d_out, int out_size) {
    const float* patch = (const float*)d_in[0];  // [676, 384]
    const float* lib   = (const float*)d_in[1];  // [100000, 384]
    float* out = (float*)d_out;                  // [0]=s, [1..50176]=s_map

    float* x2p; cudaGetSymbolAddress((void**)&x2p, g_x2);
    float* y2p; cudaGetSymbolAddress((void**)&y2p, g_y2);
    __nv_bfloat16* libbf;   cudaGetSymbolAddress((void**)&libbf, g_libbf);
    __nv_bfloat16* patchbf; cudaGetSymbolAddress((void**)&patchbf, g_patchbf);

    static int smem_set = 0;
    if (!smem_set) {
        cudaFuncSetAttribute(k_gemm_bf16, cudaFuncAttributeMaxDynamicSharedMemorySize, SMEM_GEMM);
        smem_set = 1;
    }

    k_convert<<<(M_LIB * 32 + 255) / 256, 256>>>(lib, libbf, y2p, M_LIB, 0);
    k_convert<<<(N_PATCH * 32 + 255) / 256, 256>>>(patch, patchbf, x2p, N_PATCH, 1);

    k_gemm_bf16<<<dim3(NBLK_N, NBLK_M), NTHREADS, SMEM_GEMM>>>();

    k_reduce<<<1, 1024>>>();
    k_wdist_bf16<<<(M_LIB * 32 + 255) / 256, 256>>>();
    k_top8_scalar<<<1, 1024>>>(patch, lib, out);

    k_smap<<<1, 256>>>(out + 1);
}

// round 12
// speedup vs baseline: 1.4328x; 1.4328x over previous
#include <cuda_runtime.h>
#include <cuda_bf16.h>
#include <math.h>
#include <stdint.h>

// ---------------- problem constants ----------------
#define N_PATCH 676          // 26*26
#define DIMV    384
#define M_LIB   100000
#define FMAP    26
#define IMG     224
#define KSIZE   33
#define KHALF   16
#define NCAND   8
#define S1_BLOCKS 128
#define S1_CHUNK  784        // 128*784 = 100352 >= 100000

#define TILE_M  128          // lib rows per CTA
#define TILE_N  128          // patch cols per CTA
#define BK      64           // K slice per cp.async stage
#define NKK     (DIMV / BK)  // 6
#define NBLK_M  ((M_LIB + TILE_M - 1) / TILE_M)   // 782
#define NBLK_N  ((N_PATCH + TILE_N - 1) / TILE_N) // 6
#define NTHREADS 256

// smem row pitch for BK=64 bf16: 128B data + 16B pad = 144B
#define PITCH   144

#define OFF_Y2     0
#define OFF_MINCOL 512
#define OFF_A0     2048
#define OFF_A1     (OFF_A0 + TILE_M * PITCH)
#define OFF_B0     (OFF_A1 + TILE_M * PITCH)
#define OFF_B1     (OFF_B0 + TILE_N * PITCH)
#define SMEM_GEMM  (OFF_B1 + TILE_N * PITCH)  // 75776 (~74KB) -> 2 CTAs/SM

#define U64MAX 0xFFFFFFFFFFFFFFFFull

// ---------------- device scratch ----------------
__device__ __align__(16) __nv_bfloat16 g_libbf[(size_t)M_LIB * DIMV];
__device__ __align__(16) __nv_bfloat16 g_patchbf[N_PATCH * DIMV];
__device__ unsigned long long g_min[N_PATCH];
__device__ float              g_x2[N_PATCH];
__device__ float              g_y2[M_LIB];
__device__ float              g_minval[N_PATCH];
__device__ float              g_s_star;
__device__ int                g_sidx;
__device__ int                g_mstar;
__device__ unsigned long long g_wpack[M_LIB];
__device__ unsigned long long g_cand8[S1_BLOCKS * NCAND];

// ---------------- helpers ----------------
__device__ __forceinline__ unsigned int fenc(float f) {
    unsigned int u = __float_as_uint(f);
    return (u & 0x80000000u) ? ~u : (u | 0x80000000u);
}
__device__ __forceinline__ float fdec(unsigned int k) {
    unsigned int u = (k & 0x80000000u) ? (k ^ 0x80000000u) : ~k;
    return __uint_as_float(u);
}
__device__ __forceinline__ uint32_t smem_u32(const void* p) {
    uint32_t a;
    asm("{ .reg .u64 t; cvta.to.shared.u64 t, %1; cvt.u32.u64 %0, t; }" : "=r"(a) : "l"(p));
    return a;
}
__device__ __forceinline__ void ldsm4(uint32_t a, uint32_t& r0, uint32_t& r1, uint32_t& r2, uint32_t& r3) {
    asm volatile("ldmatrix.sync.aligned.m8n8.x4.shared.b16 {%0,%1,%2,%3}, [%4];"
                 : "=r"(r0), "=r"(r1), "=r"(r2), "=r"(r3) : "r"(a));
}
__device__ __forceinline__ void mma16816(float* c, uint32_t a0, uint32_t a1, uint32_t a2, uint32_t a3,
                                         uint32_t b0, uint32_t b1) {
    asm volatile("mma.sync.aligned.m16n8k16.row.col.f32.bf16.bf16.f32 "
                 "{%0,%1,%2,%3}, {%4,%5,%6,%7}, {%8,%9}, {%0,%1,%2,%3};"
                 : "+f"(c[0]), "+f"(c[1]), "+f"(c[2]), "+f"(c[3])
                 : "r"(a0), "r"(a1), "r"(a2), "r"(a3), "r"(b0), "r"(b1));
}
__device__ __forceinline__ void cpa16(uint32_t dst, const void* src, int ok) {
    asm volatile("cp.async.cg.shared.global [%0], [%1], 16, %2;"
                 :: "r"(dst), "l"(src), "r"(ok ? 16 : 0) : "memory");
}
#define CP_COMMIT() asm volatile("cp.async.commit_group;" ::: "memory")
#define CP_WAIT1()  asm volatile("cp.async.wait_group 1;" ::: "memory")
#define CP_WAIT0()  asm volatile("cp.async.wait_group 0;" ::: "memory")

// ---------------- fp32 -> bf16 + squared norms (warp per row); optional g_min init ----------------
__global__ void k_convert(const float* __restrict__ src, __nv_bfloat16* __restrict__ dst,
                          float* __restrict__ norms, int rows, int init_min) {
    int warp = (blockIdx.x * blockDim.x + threadIdx.x) >> 5;
    int lane = threadIdx.x & 31;
    if (warp >= rows) return;
    if (init_min && lane == 1 && warp < N_PATCH) g_min[warp] = U64MAX;
    const float4* p = (const float4*)(src + (size_t)warp * DIMV);
    __nv_bfloat162* q = (__nv_bfloat162*)(dst + (size_t)warp * DIMV);
    float s = 0.f;
    #pragma unroll 3
    for (int i = lane; i < DIMV / 4; i += 32) {
        float4 v = p[i];
        s += v.x * v.x + v.y * v.y + v.z * v.z + v.w * v.w;
        q[i * 2]     = __floats2bfloat162_rn(v.x, v.y);
        q[i * 2 + 1] = __floats2bfloat162_rn(v.z, v.w);
    }
    #pragma unroll
    for (int o = 16; o; o >>= 1) s += __shfl_xor_sync(0xFFFFFFFFu, s, o);
    if (lane == 0) norms[warp] = s;
}

// ---------------- streaming bf16 HMMA GEMM + per-patch min ----------------
// 256 threads, 8 warps (2M x 4N), warp tile 64(M) x 32(N), CTA 128M x 128N.
// K streamed in 6 BK=64 slices, cp.async double-buffered. 2 CTAs/SM for pipe overlap.
__global__ __launch_bounds__(NTHREADS, 2) void k_gemm_bf16() {
    extern __shared__ char smem[];
    const uint32_t sb = smem_u32(smem);
    const int tid  = threadIdx.x;
    const int wid  = tid >> 5;
    const int lane = tid & 31;
    const int m0   = blockIdx.y * TILE_M;
    const int n0   = blockIdx.x * TILE_N;
    const int wm   = wid & 1;        // 2 warps in M (64 rows each)
    const int wn   = wid >> 1;       // 4 warps in N (32 cols each)

    if (tid < TILE_M) {
        int m = m0 + tid;
        *(float*)(smem + OFF_Y2 + tid * 4) = (m < M_LIB) ? g_y2[m] : __int_as_float(0x7F800000);
    }
    if (tid < TILE_N) *(unsigned long long*)(smem + OFF_MINCOL + tid * 8) = U64MAX;

    const int r0 = tid >> 3;
    const int cu = tid & 7;

    auto load_stage = [&](int kk, uint32_t aOff, uint32_t bOff) {
        const int kcol = kk * BK + cu * 8;
        #pragma unroll
        for (int i = 0; i < 4; i++) {
            int r = r0 + i * 32;
            int m = m0 + r;
            const void* s = g_libbf + (size_t)(m < M_LIB ? m : 0) * DIMV + kcol;
            cpa16(sb + aOff + r * PITCH + cu * 16, s, m < M_LIB);
        }
        #pragma unroll
        for (int i = 0; i < 4; i++) {
            int r = r0 + i * 32;
            int n = n0 + r;
            const void* s = g_patchbf + (size_t)(n < N_PATCH ? n : 0) * DIMV + kcol;
            cpa16(sb + bOff + r * PITCH + cu * 16, s, n < N_PATCH);
        }
        CP_COMMIT();
    };

    const uint32_t aRow = lane & 15, aSel = lane >> 4;
    uint32_t aRel[4];
    #pragma unroll
    for (int mt = 0; mt < 4; mt++)
        aRel[mt] = (wm * 64 + mt * 16 + aRow) * PITCH + aSel * 16;
    const uint32_t bRow = (lane & 7) + ((lane >> 4) << 3);
    const uint32_t bSel = (lane >> 3) & 1;
    uint32_t bRel[2];
    #pragma unroll
    for (int nt = 0; nt < 2; nt++)
        bRel[nt] = (wn * 32 + nt * 16 + bRow) * PITCH + bSel * 16;

    float acc[4][4][4];
    #pragma unroll
    for (int mt = 0; mt < 4; mt++)
        #pragma unroll
        for (int t = 0; t < 4; t++)
            #pragma unroll
            for (int e = 0; e < 4; e++) acc[mt][t][e] = 0.f;

    load_stage(0, OFF_A0, OFF_B0);

    int cur = 0;
    #pragma unroll 1
    for (int kk = 0; kk < NKK; kk++) {
        if (kk + 1 < NKK)
            load_stage(kk + 1, cur ? OFF_A0 : OFF_A1, cur ? OFF_B0 : OFF_B1);
        if (kk + 1 < NKK) CP_WAIT1(); else CP_WAIT0();
        __syncthreads();

        const uint32_t aBuf = sb + (cur ? OFF_A1 : OFF_A0);
        const uint32_t bBuf = sb + (cur ? OFF_B1 : OFF_B0);
        #pragma unroll
        for (int ks = 0; ks < BK / 16; ks++) {
            const uint32_t koff = ks * 32;
            uint32_t a[4][4];
            #pragma unroll
            for (int mt = 0; mt < 4; mt++)
                ldsm4(aBuf + aRel[mt] + koff, a[mt][0], a[mt][1], a[mt][2], a[mt][3]);
            uint32_t b[2][4];
            #pragma unroll
            for (int nt = 0; nt < 2; nt++)
                ldsm4(bBuf + bRel[nt] + koff, b[nt][0], b[nt][1], b[nt][2], b[nt][3]);
            #pragma unroll
            for (int mt = 0; mt < 4; mt++)
                #pragma unroll
                for (int nt = 0; nt < 2; nt++) {
                    mma16816(acc[mt][nt * 2],     a[mt][0], a[mt][1], a[mt][2], a[mt][3], b[nt][0], b[nt][1]);
                    mma16816(acc[mt][nt * 2 + 1], a[mt][0], a[mt][1], a[mt][2], a[mt][3], b[nt][2], b[nt][3]);
                }
        }
        __syncthreads();
        cur ^= 1;
    }

    // epilogue
    const int g  = lane >> 2;
    const int c2 = (lane & 3) * 2;
    float y2r[4][2];
    unsigned int mrow[4][2];
    #pragma unroll
    for (int mt = 0; mt < 4; mt++) {
        int ml = wm * 64 + mt * 16 + g;
        y2r[mt][0] = *(const float*)(smem + OFF_Y2 + ml * 4);
        y2r[mt][1] = *(const float*)(smem + OFF_Y2 + (ml + 8) * 4);
        mrow[mt][0] = (unsigned int)(m0 + ml);
        mrow[mt][1] = (unsigned int)(m0 + ml + 8);
    }
    #pragma unroll
    for (int t = 0; t < 4; t++) {
        #pragma unroll
        for (int j = 0; j < 2; j++) {
            unsigned long long p = U64MAX;
            #pragma unroll
            for (int mt = 0; mt < 4; mt++) {
                float v0 = fmaf(-2.f, acc[mt][t][j],     y2r[mt][0]);
                float v1 = fmaf(-2.f, acc[mt][t][j + 2], y2r[mt][1]);
                unsigned long long p0 = ((unsigned long long)fenc(v0) << 32) | mrow[mt][0];
                unsigned long long p1 = ((unsigned long long)fenc(v1) << 32) | mrow[mt][1];
                p = min(p, min(p0, p1));
            }
            #pragma unroll
            for (int o = 4; o <= 16; o <<= 1)
                p = min(p, __shfl_xor_sync(0xFFFFFFFFu, p, o));
            if (lane < 4) {
                int nb = wn * 32 + t * 8 + c2 + j;
                atomicMin((unsigned long long*)(smem + OFF_MINCOL + nb * 8), p);
            }
        }
    }
    __syncthreads();
    if (tid < TILE_N) {
        int n = n0 + tid;
        if (n < N_PATCH)
            atomicMin(&g_min[n], *(unsigned long long*)(smem + OFF_MINCOL + tid * 8));
    }
}

// ---------------- reduce: min_val, argmax -> s_idx, s_star, m_star ----------------
__global__ __launch_bounds__(1024) void k_reduce() {
    __shared__ unsigned long long sh[1024];
    int t = threadIdx.x;
    unsigned long long pk = 0ull;
    if (t < N_PATCH) {
        unsigned long long p = g_min[t];
        float score = fdec((unsigned int)(p >> 32));
        float d = sqrtf(fmaxf(g_x2[t] + score, 0.f));
        g_minval[t] = d;
        pk = ((unsigned long long)fenc(d) << 32) | (unsigned int)(0xFFFFFFFFu - t);
    }
    sh[t] = pk;
    __syncthreads();
    for (int o = 512; o; o >>= 1) {
        if (t < o) sh[t] = max(sh[t], sh[t + o]);
        __syncthreads();
    }
    if (t == 0) {
        unsigned long long w = sh[0];
        int sidx = (int)(0xFFFFFFFFu - (unsigned int)(w & 0xFFFFFFFFu));
        g_sidx = sidx;
        g_s_star = fdec((unsigned int)(w >> 32));
        g_mstar = (int)(unsigned int)(g_min[sidx] & 0xFFFFFFFFu);
    }
}

// ---------------- w_dist on bf16 lib (warp per row) — nominates candidates only ----------------
__global__ void k_wdist_bf16() {
    int warp = (blockIdx.x * blockDim.x + threadIdx.x) >> 5;
    int lane = threadIdx.x & 31;
    if (warp >= M_LIB) return;
    const uint2* pm = (const uint2*)(g_libbf + (size_t)g_mstar * DIMV);
    const uint2* pb = (const uint2*)(g_libbf + (size_t)warp * DIMV);
    float s = 0.f;
    #pragma unroll 3
    for (int i = lane; i < DIMV / 4; i += 32) {
        uint2 am = pm[i], ab = pb[i];
        float2 m0 = __bfloat1622float2(*(__nv_bfloat162*)&am.x);
        float2 m1 = __bfloat1622float2(*(__nv_bfloat162*)&am.y);
        float2 b0 = __bfloat1622float2(*(__nv_bfloat162*)&ab.x);
        float2 b1 = __bfloat1622float2(*(__nv_bfloat162*)&ab.y);
        float d0 = m0.x - b0.x, d1 = m0.y - b0.y, d2 = m1.x - b1.x, d3 = m1.y - b1.y;
        s += d0 * d0 + d1 * d1 + d2 * d2 + d3 * d3;
    }
    #pragma unroll
    for (int o = 16; o; o >>= 1) s += __shfl_xor_sync(0xFFFFFFFFu, s, o);
    if (lane == 0)
        g_wpack[warp] = ((unsigned long long)fenc(sqrtf(s)) << 32) | (unsigned int)warp;
}

// ---------------- top-8 stage 1: 128 CTAs, each selects local top-8 of its slice in smem ----------------
__global__ __launch_bounds__(256) void k_top8_s1() {
    __shared__ unsigned long long sl[S1_CHUNK];
    __shared__ unsigned long long red[256];
    const int b = blockIdx.x, t = threadIdx.x;
    const int base = b * S1_CHUNK;
    for (int i = t; i < S1_CHUNK; i += 256) {
        int m = base + i;
        sl[i] = (m < M_LIB) ? g_wpack[m] : U64MAX;
    }
    __syncthreads();
    for (int pass = 0; pass < NCAND; pass++) {
        unsigned long long loc = U64MAX;
        #pragma unroll
        for (int i = t; i < S1_CHUNK; i += 256) loc = min(loc, sl[i]);
        red[t] = loc;
        __syncthreads();
        for (int o = 128; o; o >>= 1) {
            if (t < o) red[t] = min(red[t], red[t + o]);
            __syncthreads();
        }
        unsigned long long w = red[0];
        #pragma unroll
        for (int i = t; i < S1_CHUNK; i += 256)
            if (sl[i] == w) sl[i] = U64MAX;
        if (t == 0) g_cand8[b * NCAND + pass] = w;
        __syncthreads();
    }
}

// ---------------- stage 2: reduce 1024 candidates -> top-8 -> exact fp32 re-rank -> scalar s ----------------
__global__ __launch_bounds__(1024) void k_top8_scalar(const float* __restrict__ A,
                                                      const float* __restrict__ B,
                                                      float* __restrict__ out) {
    __shared__ unsigned long long sh[1024];
    __shared__ int cand[NCAND];
    __shared__ float cd[NCAND];
    __shared__ float td[NCAND];
    int t = threadIdx.x;

    unsigned long long val = g_cand8[t];   // 1024 = S1_BLOCKS * NCAND
    for (int pass = 0; pass < NCAND; pass++) {
        sh[t] = val;
        __syncthreads();
        for (int o = 512; o; o >>= 1) {
            if (t < o) sh[t] = min(sh[t], sh[t + o]);
            __syncthreads();
        }
        unsigned long long w = sh[0];
        if (t == 0) cand[pass] = (int)(unsigned int)(w & 0xFFFFFFFFu);
        if (val == w) val = U64MAX;
        __syncthreads();
    }

    // exact fp32 distances for the 8 candidates (warp w -> candidate w)
    int warp = t >> 5, lane = t & 31;
    if (warp < NCAND) {
        int nn = cand[warp];
        const float* pm = B + (size_t)g_mstar * DIMV;
        const float* pa = A + (size_t)g_sidx * DIMV;
        const float* pb = B + (size_t)nn * DIMV;
        float sw = 0.f, st = 0.f;
        for (int i = lane; i < DIMV; i += 32) {
            float b = pb[i];
            float dw = pm[i] - b;
            float dt = pa[i] - b;
            sw += dw * dw;
            st += dt * dt;
        }
        #pragma unroll
        for (int o = 16; o; o >>= 1) {
            sw += __shfl_xor_sync(0xFFFFFFFFu, sw, o);
            st += __shfl_xor_sync(0xFFFFFFFFu, st, o);
        }
        if (lane == 0) { cd[warp] = sqrtf(sw); td[warp] = sqrtf(st); }
    }
    __syncthreads();
    if (t == 0) {
        int order[NCAND];
        #pragma unroll
        for (int i = 0; i < NCAND; i++) order[i] = i;
        for (int i = 0; i < 3; i++) {
            int best = i;
            for (int j = i + 1; j < NCAND; j++) {
                int a = order[j], b = order[best];
                if (cd[a] < cd[b] || (cd[a] == cd[b] && cand[a] < cand[b])) best = j;
            }
            int tmp = order[i]; order[i] = order[best]; order[best] = tmp;
        }
        float sd1 = td[order[1]], sd2 = td[order[2]];
        float Ds = sqrtf((float)DIMV);
        float sstar = g_s_star;
        float w = 1.f - expf(sstar / Ds) / (expf(sd1 / Ds) + expf(sd2 / Ds));
        out[0] = w * sstar;
    }
}

// ---------------- fused seg-map: out = W * M * W^T  (W = gauss(reflect) o bilinear) ----------------
__device__ __forceinline__ int reflect_idx(int i) {
    if (i < 0) i = -i;
    if (i > IMG - 1) i = 2 * (IMG - 1) - i;
    return i;
}

__global__ __launch_bounds__(256) void k_smap(float* __restrict__ out) {
    __shared__ float sK[KSIZE];
    __shared__ float sW[IMG * FMAP];
    __shared__ float sT[FMAP * IMG];
    int t = threadIdx.x;

    if (t == 0) {
        double k[KSIZE]; double s = 0.0;
        for (int i = 0; i < KSIZE; i++) {
            double x = (double)i - (KSIZE - 1) / 2.0;
            k[i] = exp(-0.5 * (x / 4.0) * (x / 4.0));
            s += k[i];
        }
        for (int i = 0; i < KSIZE; i++) sK[i] = (float)(k[i] / s);
    }
    __syncthreads();

    const float scale = (float)FMAP / (float)IMG;
    for (int idx = t; idx < IMG * FMAP; idx += 256) {
        int o = idx / FMAP, f = idx % FMAP;
        float w = 0.f;
        #pragma unroll 1
        for (int k = 0; k < KSIZE; k++) {
            int i = reflect_idx(o + k - KHALF);
            float sy = (i + 0.5f) * scale - 0.5f;
            int y0 = (int)floorf(sy);
            float wy = sy - (float)y0;
            int y0c = min(max(y0, 0), FMAP - 1);
            int y1c = min(max(y0 + 1, 0), FMAP - 1);
            float contrib = ((y0c == f) ? (1.f - wy) : 0.f) + ((y1c == f) ? wy : 0.f);
            w += sK[k] * contrib;
        }
        sW[idx] = w;
    }
    __syncthreads();

    for (int idx = t; idx < FMAP * IMG; idx += 256) {
        int f = idx / IMG, o = idx % IMG;
        float s = 0.f;
        #pragma unroll
        for (int g = 0; g < FMAP; g++)
            s += g_minval[f * FMAP + g] * sW[o * FMAP + g];
        sT[f * IMG + o] = s;
    }
    __syncthreads();

    for (int idx = t; idx < IMG * IMG; idx += 256) {
        int y = idx / IMG, x = idx % IMG;
        float s = 0.f;
        #pragma unroll
        for (int f = 0; f < FMAP; f++)
            s += sW[y * FMAP + f] * sT[f * IMG + x];
        out[idx] = s;
    }
}

// ---------------- launch ----------------
extern "C" void kernel_launch(void* const* d_in, const int* in_sizes, int n_in,
                              void* d_out, int out_size) {
    const float* patch = (const float*)d_in[0];  // [676, 384]
    const float* lib   = (const float*)d_in[1];  // [100000, 384]
    float* out = (float*)d_out;                  // [0]=s, [1..50176]=s_map

    float* x2p; cudaGetSymbolAddress((void**)&x2p, g_x2);
    float* y2p; cudaGetSymbolAddress((void**)&y2p, g_y2);
    __nv_bfloat16* libbf;   cudaGetSymbolAddress((void**)&libbf, g_libbf);
    __nv_bfloat16* patchbf; cudaGetSymbolAddress((void**)&patchbf, g_patchbf);

    static int smem_set = 0;
    if (!smem_set) {
        cudaFuncSetAttribute(k_gemm_bf16, cudaFuncAttributeMaxDynamicSharedMemorySize, SMEM_GEMM);
        smem_set = 1;
    }

    k_convert<<<(M_LIB * 32 + 255) / 256, 256>>>(lib, libbf, y2p, M_LIB, 0);
    k_convert<<<(N_PATCH * 32 + 255) / 256, 256>>>(patch, patchbf, x2p, N_PATCH, 1);

    k_gemm_bf16<<<dim3(NBLK_N, NBLK_M), NTHREADS, SMEM_GEMM>>>();

    k_reduce<<<1, 1024>>>();
    k_wdist_bf16<<<(M_LIB * 32 + 255) / 256, 256>>>();
    k_top8_s1<<<S1_BLOCKS, 256>>>();
    k_top8_scalar<<<1, 1024>>>(patch, lib, out);

    k_smap<<<1, 256>>>(out + 1);
}

// round 13
// speedup vs baseline: 1.9407x; 1.3545x over previous
#include <cuda_runtime.h>
#include <cuda_bf16.h>
#include <math.h>
#include <stdint.h>

// ---------------- problem constants ----------------
#define N_PATCH 676          // 26*26
#define DIMV    384
#define M_LIB   100000
#define FMAP    26
#define IMG     224
#define KSIZE   33
#define KHALF   16
#define NCAND   8
#define S1_BLOCKS 128
#define S1_CHUNK  784        // 128*784 = 100352 >= 100000

#define TILE_M  128          // lib rows per CTA
#define TILE_N  128          // patch cols per CTA
#define BK      64           // K slice per cp.async stage
#define NKK     (DIMV / BK)  // 6
#define NBLK_M  ((M_LIB + TILE_M - 1) / TILE_M)   // 782
#define NBLK_N  ((N_PATCH + TILE_N - 1) / TILE_N) // 6
#define NTHREADS 256

// smem row pitch for BK=64 bf16: 128B data + 16B pad = 144B
#define PITCH   144

#define OFF_Y2     0
#define OFF_MINCOL 512
#define OFF_A0     2048
#define OFF_A1     (OFF_A0 + TILE_M * PITCH)
#define OFF_B0     (OFF_A1 + TILE_M * PITCH)
#define OFF_B1     (OFF_B0 + TILE_N * PITCH)
#define SMEM_GEMM  (OFF_B1 + TILE_N * PITCH)  // 75776 (~74KB) -> 2 CTAs/SM

#define U64MAX 0xFFFFFFFFFFFFFFFFull

// ---------------- device scratch ----------------
__device__ __align__(16) __nv_bfloat16 g_libbf[(size_t)M_LIB * DIMV];
__device__ __align__(16) __nv_bfloat16 g_patchbf[N_PATCH * DIMV];
__device__ unsigned long long g_min[N_PATCH];
__device__ float              g_x2[N_PATCH];
__device__ float              g_y2[M_LIB];
__device__ float              g_minval[N_PATCH];
__device__ float              g_s_star;
__device__ int                g_sidx;
__device__ int                g_mstar;
__device__ unsigned long long g_wpack[M_LIB];
__device__ unsigned long long g_cand8[S1_BLOCKS * NCAND];
__device__ float              g_k1d[KSIZE];
__device__ float              g_up[IMG * IMG];
__device__ float              g_tmp[IMG * IMG];

// ---------------- helpers ----------------
__device__ __forceinline__ unsigned int fenc(float f) {
    unsigned int u = __float_as_uint(f);
    return (u & 0x80000000u) ? ~u : (u | 0x80000000u);
}
__device__ __forceinline__ float fdec(unsigned int k) {
    unsigned int u = (k & 0x80000000u) ? (k ^ 0x80000000u) : ~k;
    return __uint_as_float(u);
}
__device__ __forceinline__ uint32_t smem_u32(const void* p) {
    uint32_t a;
    asm("{ .reg .u64 t; cvta.to.shared.u64 t, %1; cvt.u32.u64 %0, t; }" : "=r"(a) : "l"(p));
    return a;
}
__device__ __forceinline__ void ldsm4(uint32_t a, uint32_t& r0, uint32_t& r1, uint32_t& r2, uint32_t& r3) {
    asm volatile("ldmatrix.sync.aligned.m8n8.x4.shared.b16 {%0,%1,%2,%3}, [%4];"
                 : "=r"(r0), "=r"(r1), "=r"(r2), "=r"(r3) : "r"(a));
}
__device__ __forceinline__ void mma16816(float* c, uint32_t a0, uint32_t a1, uint32_t a2, uint32_t a3,
                                         uint32_t b0, uint32_t b1) {
    asm volatile("mma.sync.aligned.m16n8k16.row.col.f32.bf16.bf16.f32 "
                 "{%0,%1,%2,%3}, {%4,%5,%6,%7}, {%8,%9}, {%0,%1,%2,%3};"
                 : "+f"(c[0]), "+f"(c[1]), "+f"(c[2]), "+f"(c[3])
                 : "r"(a0), "r"(a1), "r"(a2), "r"(a3), "r"(b0), "r"(b1));
}
__device__ __forceinline__ void cpa16(uint32_t dst, const void* src, int ok) {
    asm volatile("cp.async.cg.shared.global [%0], [%1], 16, %2;"
                 :: "r"(dst), "l"(src), "r"(ok ? 16 : 0) : "memory");
}
#define CP_COMMIT() asm volatile("cp.async.commit_group;" ::: "memory")
#define CP_WAIT1()  asm volatile("cp.async.wait_group 1;" ::: "memory")
#define CP_WAIT0()  asm volatile("cp.async.wait_group 0;" ::: "memory")

// ---------------- fp32 -> bf16 + squared norms (warp per row) ----------------
// flag==1: also init g_min. flag==2: block 0 / thread 0 also builds g_k1d.
__global__ void k_convert(const float* __restrict__ src, __nv_bfloat16* __restrict__ dst,
                          float* __restrict__ norms, int rows, int flag) {
    int warp = (blockIdx.x * blockDim.x + threadIdx.x) >> 5;
    int lane = threadIdx.x & 31;
    if (flag == 2 && blockIdx.x == 0 && threadIdx.x == 0) {
        double k[KSIZE]; double s = 0.0;
        for (int i = 0; i < KSIZE; i++) {
            double x = (double)i - (KSIZE - 1) / 2.0;
            k[i] = exp(-0.5 * (x / 4.0) * (x / 4.0));
            s += k[i];
        }
        for (int i = 0; i < KSIZE; i++) g_k1d[i] = (float)(k[i] / s);
    }
    if (warp >= rows) return;
    if (flag == 1 && lane == 1 && warp < N_PATCH) g_min[warp] = U64MAX;
    const float4* p = (const float4*)(src + (size_t)warp * DIMV);
    __nv_bfloat162* q = (__nv_bfloat162*)(dst + (size_t)warp * DIMV);
    float s = 0.f;
    #pragma unroll 3
    for (int i = lane; i < DIMV / 4; i += 32) {
        float4 v = p[i];
        s += v.x * v.x + v.y * v.y + v.z * v.z + v.w * v.w;
        q[i * 2]     = __floats2bfloat162_rn(v.x, v.y);
        q[i * 2 + 1] = __floats2bfloat162_rn(v.z, v.w);
    }
    #pragma unroll
    for (int o = 16; o; o >>= 1) s += __shfl_xor_sync(0xFFFFFFFFu, s, o);
    if (lane == 0) norms[warp] = s;
}

// ---------------- streaming bf16 HMMA GEMM + per-patch min (round-9 proven) ----------------
__global__ __launch_bounds__(NTHREADS, 2) void k_gemm_bf16() {
    extern __shared__ char smem[];
    const uint32_t sb = smem_u32(smem);
    const int tid  = threadIdx.x;
    const int wid  = tid >> 5;
    const int lane = tid & 31;
    const int m0   = blockIdx.y * TILE_M;
    const int n0   = blockIdx.x * TILE_N;
    const int wm   = wid & 1;        // 2 warps in M (64 rows each)
    const int wn   = wid >> 1;       // 4 warps in N (32 cols each)

    if (tid < TILE_M) {
        int m = m0 + tid;
        *(float*)(smem + OFF_Y2 + tid * 4) = (m < M_LIB) ? g_y2[m] : __int_as_float(0x7F800000);
    }
    if (tid < TILE_N) *(unsigned long long*)(smem + OFF_MINCOL + tid * 8) = U64MAX;

    const int r0 = tid >> 3;
    const int cu = tid & 7;

    auto load_stage = [&](int kk, uint32_t aOff, uint32_t bOff) {
        const int kcol = kk * BK + cu * 8;
        #pragma unroll
        for (int i = 0; i < 4; i++) {
            int r = r0 + i * 32;
            int m = m0 + r;
            const void* s = g_libbf + (size_t)(m < M_LIB ? m : 0) * DIMV + kcol;
            cpa16(sb + aOff + r * PITCH + cu * 16, s, m < M_LIB);
        }
        #pragma unroll
        for (int i = 0; i < 4; i++) {
            int r = r0 + i * 32;
            int n = n0 + r;
            const void* s = g_patchbf + (size_t)(n < N_PATCH ? n : 0) * DIMV + kcol;
            cpa16(sb + bOff + r * PITCH + cu * 16, s, n < N_PATCH);
        }
        CP_COMMIT();
    };

    const uint32_t aRow = lane & 15, aSel = lane >> 4;
    uint32_t aRel[4];
    #pragma unroll
    for (int mt = 0; mt < 4; mt++)
        aRel[mt] = (wm * 64 + mt * 16 + aRow) * PITCH + aSel * 16;
    const uint32_t bRow = (lane & 7) + ((lane >> 4) << 3);
    const uint32_t bSel = (lane >> 3) & 1;
    uint32_t bRel[2];
    #pragma unroll
    for (int nt = 0; nt < 2; nt++)
        bRel[nt] = (wn * 32 + nt * 16 + bRow) * PITCH + bSel * 16;

    float acc[4][4][4];
    #pragma unroll
    for (int mt = 0; mt < 4; mt++)
        #pragma unroll
        for (int t = 0; t < 4; t++)
            #pragma unroll
            for (int e = 0; e < 4; e++) acc[mt][t][e] = 0.f;

    load_stage(0, OFF_A0, OFF_B0);

    int cur = 0;
    #pragma unroll 1
    for (int kk = 0; kk < NKK; kk++) {
        if (kk + 1 < NKK)
            load_stage(kk + 1, cur ? OFF_A0 : OFF_A1, cur ? OFF_B0 : OFF_B1);
        if (kk + 1 < NKK) CP_WAIT1(); else CP_WAIT0();
        __syncthreads();

        const uint32_t aBuf = sb + (cur ? OFF_A1 : OFF_A0);
        const uint32_t bBuf = sb + (cur ? OFF_B1 : OFF_B0);
        #pragma unroll
        for (int ks = 0; ks < BK / 16; ks++) {
            const uint32_t koff = ks * 32;
            uint32_t a[4][4];
            #pragma unroll
            for (int mt = 0; mt < 4; mt++)
                ldsm4(aBuf + aRel[mt] + koff, a[mt][0], a[mt][1], a[mt][2], a[mt][3]);
            uint32_t b[2][4];
            #pragma unroll
            for (int nt = 0; nt < 2; nt++)
                ldsm4(bBuf + bRel[nt] + koff, b[nt][0], b[nt][1], b[nt][2], b[nt][3]);
            #pragma unroll
            for (int mt = 0; mt < 4; mt++)
                #pragma unroll
                for (int nt = 0; nt < 2; nt++) {
                    mma16816(acc[mt][nt * 2],     a[mt][0], a[mt][1], a[mt][2], a[mt][3], b[nt][0], b[nt][1]);
                    mma16816(acc[mt][nt * 2 + 1], a[mt][0], a[mt][1], a[mt][2], a[mt][3], b[nt][2], b[nt][3]);
                }
        }
        __syncthreads();
        cur ^= 1;
    }

    // epilogue
    const int g  = lane >> 2;
    const int c2 = (lane & 3) * 2;
    float y2r[4][2];
    unsigned int mrow[4][2];
    #pragma unroll
    for (int mt = 0; mt < 4; mt++) {
        int ml = wm * 64 + mt * 16 + g;
        y2r[mt][0] = *(const float*)(smem + OFF_Y2 + ml * 4);
        y2r[mt][1] = *(const float*)(smem + OFF_Y2 + (ml + 8) * 4);
        mrow[mt][0] = (unsigned int)(m0 + ml);
        mrow[mt][1] = (unsigned int)(m0 + ml + 8);
    }
    #pragma unroll
    for (int t = 0; t < 4; t++) {
        #pragma unroll
        for (int j = 0; j < 2; j++) {
            unsigned long long p = U64MAX;
            #pragma unroll
            for (int mt = 0; mt < 4; mt++) {
                float v0 = fmaf(-2.f, acc[mt][t][j],     y2r[mt][0]);
                float v1 = fmaf(-2.f, acc[mt][t][j + 2], y2r[mt][1]);
                unsigned long long p0 = ((unsigned long long)fenc(v0) << 32) | mrow[mt][0];
                unsigned long long p1 = ((unsigned long long)fenc(v1) << 32) | mrow[mt][1];
                p = min(p, min(p0, p1));
            }
            #pragma unroll
            for (int o = 4; o <= 16; o <<= 1)
                p = min(p, __shfl_xor_sync(0xFFFFFFFFu, p, o));
            if (lane < 4) {
                int nb = wn * 32 + t * 8 + c2 + j;
                atomicMin((unsigned long long*)(smem + OFF_MINCOL + nb * 8), p);
            }
        }
    }
    __syncthreads();
    if (tid < TILE_N) {
        int n = n0 + tid;
        if (n < N_PATCH)
            atomicMin(&g_min[n], *(unsigned long long*)(smem + OFF_MINCOL + tid * 8));
    }
}

// ---------------- reduce: min_val, argmax -> s_idx, s_star, m_star ----------------
__global__ __launch_bounds__(1024) void k_reduce() {
    __shared__ unsigned long long sh[1024];
    int t = threadIdx.x;
    unsigned long long pk = 0ull;
    if (t < N_PATCH) {
        unsigned long long p = g_min[t];
        float score = fdec((unsigned int)(p >> 32));
        float d = sqrtf(fmaxf(g_x2[t] + score, 0.f));
        g_minval[t] = d;
        pk = ((unsigned long long)fenc(d) << 32) | (unsigned int)(0xFFFFFFFFu - t);
    }
    sh[t] = pk;
    __syncthreads();
    for (int o = 512; o; o >>= 1) {
        if (t < o) sh[t] = max(sh[t], sh[t + o]);
        __syncthreads();
    }
    if (t == 0) {
        unsigned long long w = sh[0];
        int sidx = (int)(0xFFFFFFFFu - (unsigned int)(w & 0xFFFFFFFFu));
        g_sidx = sidx;
        g_s_star = fdec((unsigned int)(w >> 32));
        g_mstar = (int)(unsigned int)(g_min[sidx] & 0xFFFFFFFFu);
    }
}

// ---------------- w_dist on bf16 lib (warp per row) — nominates candidates only ----------------
__global__ void k_wdist_bf16() {
    int warp = (blockIdx.x * blockDim.x + threadIdx.x) >> 5;
    int lane = threadIdx.x & 31;
    if (warp >= M_LIB) return;
    const uint2* pm = (const uint2*)(g_libbf + (size_t)g_mstar * DIMV);
    const uint2* pb = (const uint2*)(g_libbf + (size_t)warp * DIMV);
    float s = 0.f;
    #pragma unroll 3
    for (int i = lane; i < DIMV / 4; i += 32) {
        uint2 am = pm[i], ab = pb[i];
        float2 m0 = __bfloat1622float2(*(__nv_bfloat162*)&am.x);
        float2 m1 = __bfloat1622float2(*(__nv_bfloat162*)&am.y);
        float2 b0 = __bfloat1622float2(*(__nv_bfloat162*)&ab.x);
        float2 b1 = __bfloat1622float2(*(__nv_bfloat162*)&ab.y);
        float d0 = m0.x - b0.x, d1 = m0.y - b0.y, d2 = m1.x - b1.x, d3 = m1.y - b1.y;
        s += d0 * d0 + d1 * d1 + d2 * d2 + d3 * d3;
    }
    #pragma unroll
    for (int o = 16; o; o >>= 1) s += __shfl_xor_sync(0xFFFFFFFFu, s, o);
    if (lane == 0)
        g_wpack[warp] = ((unsigned long long)fenc(sqrtf(s)) << 32) | (unsigned int)warp;
}

// ---------------- top-8 stage 1: 128 CTAs, local top-8 of 784-slice in smem ----------------
__global__ __launch_bounds__(256) void k_top8_s1() {
    __shared__ unsigned long long sl[S1_CHUNK];
    __shared__ unsigned long long red[256];
    const int b = blockIdx.x, t = threadIdx.x;
    const int base = b * S1_CHUNK;
    for (int i = t; i < S1_CHUNK; i += 256) {
        int m = base + i;
        sl[i] = (m < M_LIB) ? g_wpack[m] : U64MAX;
    }
    __syncthreads();
    for (int pass = 0; pass < NCAND; pass++) {
        unsigned long long loc = U64MAX;
        #pragma unroll
        for (int i = t; i < S1_CHUNK; i += 256) loc = min(loc, sl[i]);
        red[t] = loc;
        __syncthreads();
        for (int o = 128; o; o >>= 1) {
            if (t < o) red[t] = min(red[t], red[t + o]);
            __syncthreads();
        }
        unsigned long long w = red[0];
        #pragma unroll
        for (int i = t; i < S1_CHUNK; i += 256)
            if (sl[i] == w) sl[i] = U64MAX;
        if (t == 0) g_cand8[b * NCAND + pass] = w;
        __syncthreads();
    }
}

// ---------------- stage 2: 1024 candidates -> top-8 -> exact fp32 re-rank -> scalar s ----------------
__global__ __launch_bounds__(1024) void k_top8_scalar(const float* __restrict__ A,
                                                      const float* __restrict__ B,
                                                      float* __restrict__ out) {
    __shared__ unsigned long long sh[1024];
    __shared__ int cand[NCAND];
    __shared__ float cd[NCAND];
    __shared__ float td[NCAND];
    int t = threadIdx.x;

    unsigned long long val = g_cand8[t];   // 1024 = S1_BLOCKS * NCAND
    for (int pass = 0; pass < NCAND; pass++) {
        sh[t] = val;
        __syncthreads();
        for (int o = 512; o; o >>= 1) {
            if (t < o) sh[t] = min(sh[t], sh[t + o]);
            __syncthreads();
        }
        unsigned long long w = sh[0];
        if (t == 0) cand[pass] = (int)(unsigned int)(w & 0xFFFFFFFFu);
        if (val == w) val = U64MAX;
        __syncthreads();
    }

    int warp = t >> 5, lane = t & 31;
    if (warp < NCAND) {
        int nn = cand[warp];
        const float* pm = B + (size_t)g_mstar * DIMV;
        const float* pa = A + (size_t)g_sidx * DIMV;
        const float* pb = B + (size_t)nn * DIMV;
        float sw = 0.f, st = 0.f;
        for (int i = lane; i < DIMV; i += 32) {
            float b = pb[i];
            float dw = pm[i] - b;
            float dt = pa[i] - b;
            sw += dw * dw;
            st += dt * dt;
        }
        #pragma unroll
        for (int o = 16; o; o >>= 1) {
            sw += __shfl_xor_sync(0xFFFFFFFFu, sw, o);
            st += __shfl_xor_sync(0xFFFFFFFFu, st, o);
        }
        if (lane == 0) { cd[warp] = sqrtf(sw); td[warp] = sqrtf(st); }
    }
    __syncthreads();
    if (t == 0) {
        int order[NCAND];
        #pragma unroll
        for (int i = 0; i < NCAND; i++) order[i] = i;
        for (int i = 0; i < 3; i++) {
            int best = i;
            for (int j = i + 1; j < NCAND; j++) {
                int a = order[j], b = order[best];
                if (cd[a] < cd[b] || (cd[a] == cd[b] && cand[a] < cand[b])) best = j;
            }
            int tmp = order[i]; order[i] = order[best]; order[best] = tmp;
        }
        float sd1 = td[order[1]], sd2 = td[order[2]];
        float Ds = sqrtf((float)DIMV);
        float sstar = g_s_star;
        float w = 1.f - expf(sstar / Ds) / (expf(sd1 / Ds) + expf(sd2 / Ds));
        out[0] = w * sstar;
    }
}

// ---------------- bilinear upsample 26x26 -> 224x224 (parallel, round-9 proven) ----------------
__global__ void k_upsample() {
    int oy = blockIdx.x;
    int ox = threadIdx.x;
    const float scale = (float)FMAP / (float)IMG;
    float sy = (oy + 0.5f) * scale - 0.5f;
    float sx = (ox + 0.5f) * scale - 0.5f;
    int y0 = (int)floorf(sy), x0 = (int)floorf(sx);
    float wy = sy - (float)y0, wx = sx - (float)x0;
    int y0c = min(max(y0, 0), FMAP - 1), y1c = min(max(y0 + 1, 0), FMAP - 1);
    int x0c = min(max(x0, 0), FMAP - 1), x1c = min(max(x0 + 1, 0), FMAP - 1);
    float v00 = g_minval[y0c * FMAP + x0c];
    float v01 = g_minval[y0c * FMAP + x1c];
    float v10 = g_minval[y1c * FMAP + x0c];
    float v11 = g_minval[y1c * FMAP + x1c];
    float top = v00 + (v01 - v00) * wx;
    float bot = v10 + (v11 - v10) * wx;
    g_up[oy * IMG + ox] = top + (bot - top) * wy;
}

__device__ __forceinline__ int reflect_idx(int i) {
    if (i < 0) i = -i;
    if (i > IMG - 1) i = 2 * (IMG - 1) - i;
    return i;
}

__global__ void k_blur_h() {
    __shared__ float row[IMG];
    int y = blockIdx.x, x = threadIdx.x;
    row[x] = g_up[y * IMG + x];
    __syncthreads();
    float s = 0.f;
    #pragma unroll
    for (int k = 0; k < KSIZE; k++) s += g_k1d[k] * row[reflect_idx(x + k - KHALF)];
    g_tmp[y * IMG + x] = s;
}

__global__ void k_blur_v(float* __restrict__ out) {
    int y = blockIdx.x, x = threadIdx.x;
    float s = 0.f;
    #pragma unroll
    for (int k = 0; k < KSIZE; k++) s += g_k1d[k] * g_tmp[reflect_idx(y + k - KHALF) * IMG + x];
    out[y * IMG + x] = s;
}

// ---------------- launch ----------------
extern "C" void kernel_launch(void* const* d_in, const int* in_sizes, int n_in,
                              void* d_out, int out_size) {
    const float* patch = (const float*)d_in[0];  // [676, 384]
    const float* lib   = (const float*)d_in[1];  // [100000, 384]
    float* out = (float*)d_out;                  // [0]=s, [1..50176]=s_map

    float* x2p; cudaGetSymbolAddress((void**)&x2p, g_x2);
    float* y2p; cudaGetSymbolAddress((void**)&y2p, g_y2);
    __nv_bfloat16* libbf;   cudaGetSymbolAddress((void**)&libbf, g_libbf);
    __nv_bfloat16* patchbf; cudaGetSymbolAddress((void**)&patchbf, g_patchbf);

    static int smem_set = 0;
    if (!smem_set) {
        cudaFuncSetAttribute(k_gemm_bf16, cudaFuncAttributeMaxDynamicSharedMemorySize, SMEM_GEMM);
        smem_set = 1;
    }

    k_convert<<<(M_LIB * 32 + 255) / 256, 256>>>(lib, libbf, y2p, M_LIB, 2);
    k_convert<<<(N_PATCH * 32 + 255) / 256, 256>>>(patch, patchbf, x2p, N_PATCH, 1);

    k_gemm_bf16<<<dim3(NBLK_N, NBLK_M), NTHREADS, SMEM_GEMM>>>();

    k_reduce<<<1, 1024>>>();
    k_wdist_bf16<<<(M_LIB * 32 + 255) / 256, 256>>>();
    k_top8_s1<<<S1_BLOCKS, 256>>>();
    k_top8_scalar<<<1, 1024>>>(patch, lib, out);

    k_upsample<<<IMG, IMG>>>();
    k_blur_h<<<IMG, IMG>>>();
    k_blur_v<<<IMG, IMG>>>(out + 1);
}